// round 2
// baseline (speedup 1.0000x reference)
#include <cuda_runtime.h>
#include <math.h>

#define BB 32
#define TT 4096
#define DD 256
#define KK 128         // frequency count = D/2
#define HH 512         // hidden = 2*D
#define TBLK 64        // tokens per block in main kernel
#define NTHR 256

// ---------------- scratch (global __device__, no allocation) ----------------
__device__ float2 g_tab[TT];        // (cos(2*pi*m/T), sin(2*pi*m/T))
__device__ float2 g_s0c0[BB * KK];  // (sin(phase0), cos(phase0))
__device__ float  g_mag[BB * KK];   // |X| * freq_bands
__device__ float  g_base[BB * HH];  // mag @ w1[:128,:] + b1

// ---------------- kernel 0: trig table -------------------------------------
__global__ void k_tab() {
    int m = blockIdx.x * blockDim.x + threadIdx.x;
    if (m < TT) {
        float s, c;
        sincospif((float)m * (1.0f / 2048.0f), &s, &c);  // 2*pi*m/4096 = pi*m/2048
        g_tab[m] = make_float2(c, s);
    }
}

// ---------------- kernel 1: DFT (one block per (b,f)) -----------------------
__global__ void k_dft(const int* __restrict__ byte_ids,
                      const float* __restrict__ freq_bands) {
    int f = blockIdx.x;
    int b = blockIdx.y;
    int tid = threadIdx.x;  // 128 threads

    float re = 0.f, im = 0.f;
    for (int t = tid; t < TT; t += 128) {
        float s = (float)byte_ids[b * TT + t] * (1.0f / 127.5f) - 1.0f;
        int m = (f * t) & (TT - 1);
        float2 cs = g_tab[m];
        re += s * cs.x;   // e^{-i theta}: cos - i sin
        im -= s * cs.y;
    }
    // reduce 128 threads
    #pragma unroll
    for (int o = 16; o > 0; o >>= 1) {
        re += __shfl_xor_sync(0xffffffffu, re, o);
        im += __shfl_xor_sync(0xffffffffu, im, o);
    }
    __shared__ float sre[4], sim[4];
    if ((tid & 31) == 0) { sre[tid >> 5] = re; sim[tid >> 5] = im; }
    __syncthreads();
    if (tid == 0) {
        re = sre[0] + sre[1] + sre[2] + sre[3];
        im = sim[0] + sim[1] + sim[2] + sim[3];
        float mr = sqrtf(re * re + im * im);
        float s0, c0;
        if (mr > 0.f) { s0 = im / mr; c0 = re / mr; }
        else          { s0 = 0.f;    c0 = 1.f;    }
        g_mag[b * KK + f]  = mr * freq_bands[f];
        g_s0c0[b * KK + f] = make_float2(s0, c0);
    }
}

// ---------------- kernel 2: base = mag @ w1[:128] + b1 ----------------------
__global__ void k_base(const float* __restrict__ w1, const float* __restrict__ b1) {
    int b = blockIdx.x;
    int j = threadIdx.x;  // 512 threads
    __shared__ float mg[KK];
    if (threadIdx.x < KK) mg[threadIdx.x] = g_mag[b * KK + threadIdx.x];
    __syncthreads();
    float acc = b1[j];
    #pragma unroll 4
    for (int f = 0; f < KK; ++f) acc += mg[f] * w1[f * HH + j];
    g_base[b * HH + j] = acc;
}

// ---------------- kernel 3: fused feats->GEMM1->LN->GELU->GEMM2 -------------
// smem layout (floats):
//   stab   : float2[4096]           -> 8192 floats
//   sa     : [TBLK][KK+1]           -> 64*129 = 8256 floats
//   sh     : [TBLK][HH+1]           -> 64*513 = 32832 floats
//   ss0c0  : float2[KK]             -> 256 floats
#define SM_STAB 0
#define SM_SA   8192
#define SM_SH   (8192 + TBLK * (KK + 1))
#define SM_SC   (SM_SH + TBLK * (HH + 1))
#define SM_FLOATS (SM_SC + 2 * KK)

__global__ void k_main(const float* __restrict__ w1,
                       const float* __restrict__ w2,
                       const float* __restrict__ b2,
                       const float* __restrict__ gamma,
                       const float* __restrict__ beta,
                       float* __restrict__ out) {
    extern __shared__ float smem[];
    float2* stab  = (float2*)(smem + SM_STAB);
    float*  sa    = smem + SM_SA;
    float*  sh    = smem + SM_SH;
    float2* ss0c0 = (float2*)(smem + SM_SC);

    int b  = blockIdx.y;
    int t0 = blockIdx.x * TBLK;
    int tid = threadIdx.x;

    // stage trig table + per-batch phase coefficients
    for (int i = tid; i < TT; i += NTHR) stab[i] = g_tab[i];
    for (int i = tid; i < KK; i += NTHR) ss0c0[i] = g_s0c0[b * KK + i];
    __syncthreads();

    // build a[t][f] = sin(phase0[b,f] + 2*pi*f*(t0+t)/T)
    for (int e = tid; e < TBLK * KK; e += NTHR) {
        int t = e >> 7;
        int f = e & (KK - 1);
        int m = (f * (t0 + t)) & (TT - 1);
        float2 cs = stab[m];
        float2 sc = ss0c0[f];
        sa[t * (KK + 1) + f] = sc.x * cs.x + sc.y * cs.y;
    }
    __syncthreads();

    int ty = tid >> 4;      // t-group 0..15 (4 tokens each)
    int tx = tid & 15;      // j-group (8 cols each)
    const float* w1s = w1 + KK * HH;  // rows 128..255 of w1

    // ---- GEMM1: h[64][512] = a[64][128] @ w1s[128][512] + base ----
    #pragma unroll 1
    for (int pass = 0; pass < 4; ++pass) {
        int jb = pass * 128 + tx * 8;
        float acc[4][8];
        #pragma unroll
        for (int i = 0; i < 4; ++i)
            #pragma unroll
            for (int k = 0; k < 8; ++k) acc[i][k] = 0.f;

        const float* wp = w1s + jb;
        #pragma unroll 4
        for (int f = 0; f < KK; ++f) {
            float4 wa = *(const float4*)(wp + f * HH);
            float4 wb = *(const float4*)(wp + f * HH + 4);
            float av[4];
            #pragma unroll
            for (int i = 0; i < 4; ++i) av[i] = sa[(ty * 4 + i) * (KK + 1) + f];
            #pragma unroll
            for (int i = 0; i < 4; ++i) {
                acc[i][0] += av[i] * wa.x; acc[i][1] += av[i] * wa.y;
                acc[i][2] += av[i] * wa.z; acc[i][3] += av[i] * wa.w;
                acc[i][4] += av[i] * wb.x; acc[i][5] += av[i] * wb.y;
                acc[i][6] += av[i] * wb.z; acc[i][7] += av[i] * wb.w;
            }
        }
        float bse[8];
        #pragma unroll
        for (int k = 0; k < 8; ++k) bse[k] = g_base[b * HH + jb + k];
        #pragma unroll
        for (int i = 0; i < 4; ++i) {
            int t = ty * 4 + i;
            #pragma unroll
            for (int k = 0; k < 8; ++k)
                sh[t * (HH + 1) + jb + k] = acc[i][k] + bse[k];
        }
    }
    __syncthreads();

    // ---- LayerNorm + exact GELU in-place on sh ----
    {
        int row  = tid >> 2;   // 0..63
        int part = tid & 3;    // quarter of the 512 cols
        float* hr = sh + row * (HH + 1) + part * 128;
        float sum = 0.f, sq = 0.f;
        #pragma unroll 4
        for (int i = 0; i < 128; ++i) { float v = hr[i]; sum += v; sq += v * v; }
        #pragma unroll
        for (int o = 1; o < 4; o <<= 1) {
            sum += __shfl_xor_sync(0xffffffffu, sum, o);
            sq  += __shfl_xor_sync(0xffffffffu, sq,  o);
        }
        float mu  = sum * (1.0f / 512.0f);
        float var = sq * (1.0f / 512.0f) - mu * mu;
        float rs  = rsqrtf(var + 1e-5f);
        #pragma unroll 4
        for (int i = 0; i < 128; ++i) {
            int j = part * 128 + i;
            float v = (hr[i] - mu) * rs * gamma[j] + beta[j];
            hr[i] = v * normcdff(v);   // exact GELU
        }
    }
    __syncthreads();

    // ---- GEMM2: out[64][256] = g[64][512] @ w2[512][256] + b2 ----
    #pragma unroll 1
    for (int pass = 0; pass < 2; ++pass) {
        int db = pass * 128 + tx * 8;
        float acc[4][8];
        #pragma unroll
        for (int i = 0; i < 4; ++i)
            #pragma unroll
            for (int k = 0; k < 8; ++k) acc[i][k] = 0.f;

        const float* wp = w2 + db;
        #pragma unroll 4
        for (int j = 0; j < HH; ++j) {
            float4 wa = *(const float4*)(wp + j * DD);
            float4 wb = *(const float4*)(wp + j * DD + 4);
            float gv[4];
            #pragma unroll
            for (int i = 0; i < 4; ++i) gv[i] = sh[(ty * 4 + i) * (HH + 1) + j];
            #pragma unroll
            for (int i = 0; i < 4; ++i) {
                acc[i][0] += gv[i] * wa.x; acc[i][1] += gv[i] * wa.y;
                acc[i][2] += gv[i] * wa.z; acc[i][3] += gv[i] * wa.w;
                acc[i][4] += gv[i] * wb.x; acc[i][5] += gv[i] * wb.y;
                acc[i][6] += gv[i] * wb.z; acc[i][7] += gv[i] * wb.w;
            }
        }
        float4 bv0 = *(const float4*)(b2 + db);
        float4 bv1 = *(const float4*)(b2 + db + 4);
        #pragma unroll
        for (int i = 0; i < 4; ++i) {
            int t = t0 + ty * 4 + i;
            float* op = out + ((size_t)b * TT + t) * DD + db;
            float4 o0 = make_float4(acc[i][0] + bv0.x, acc[i][1] + bv0.y,
                                    acc[i][2] + bv0.z, acc[i][3] + bv0.w);
            float4 o1 = make_float4(acc[i][4] + bv1.x, acc[i][5] + bv1.y,
                                    acc[i][6] + bv1.z, acc[i][7] + bv1.w);
            *(float4*)(op)     = o0;
            *(float4*)(op + 4) = o1;
        }
    }
}

// ---------------- launch ----------------------------------------------------
extern "C" void kernel_launch(void* const* d_in, const int* in_sizes, int n_in,
                              void* d_out, int out_size) {
    const int*   byte_ids   = (const int*)d_in[0];
    const float* freq_bands = (const float*)d_in[1];
    const float* w1         = (const float*)d_in[2];
    const float* b1         = (const float*)d_in[3];
    const float* gamma      = (const float*)d_in[4];
    const float* beta       = (const float*)d_in[5];
    const float* w2         = (const float*)d_in[6];
    const float* b2         = (const float*)d_in[7];
    float* out = (float*)d_out;

    size_t smem_bytes = (size_t)SM_FLOATS * sizeof(float);  // ~198 KB
    cudaFuncSetAttribute(k_main, cudaFuncAttributeMaxDynamicSharedMemorySize,
                         (int)smem_bytes);

    k_tab<<<(TT + 255) / 256, 256>>>();
    k_dft<<<dim3(KK, BB), 128>>>(byte_ids, freq_bands);
    k_base<<<BB, HH>>>(w1, b1);
    k_main<<<dim3(TT / TBLK, BB), NTHR, smem_bytes>>>(w1, w2, b2, gamma, beta, out);
}

// round 6
// speedup vs baseline: 3.9729x; 3.9729x over previous
#include <cuda_runtime.h>
#include <math.h>

#define BB 32
#define TT 4096
#define DD 256
#define KK 128         // frequency count = D/2
#define HH 512         // hidden = 2*D
#define TBLK 64        // tokens per block in main kernel
#define NTHR 256

// ---------------- scratch (global __device__, no allocation) ----------------
__device__ float2 g_tab[TT];        // (cos(2*pi*m/T), sin(2*pi*m/T))
__device__ float2 g_s0c0[BB * KK];  // (sin(phase0), cos(phase0))
__device__ float  g_mag[BB * KK];   // |X| * freq_bands
__device__ float  g_base[BB * HH];  // mag @ w1[:128,:] + b1  (exact fp32 path)
__device__ unsigned g_w1t[KK * HH]; // tf32 bits of w1 rows 128..255
__device__ unsigned g_w2t[HH * DD]; // tf32 bits of w2

__device__ __forceinline__ unsigned f2tf32(float x) {
    unsigned r;
    asm("cvt.rna.tf32.f32 %0, %1;" : "=r"(r) : "f"(x));
    return r;
}

__device__ __forceinline__ void mma8(float* d,
                                     unsigned a0, unsigned a1, unsigned a2, unsigned a3,
                                     unsigned b0, unsigned b1) {
    asm volatile("mma.sync.aligned.m16n8k8.row.col.f32.tf32.tf32.f32 "
                 "{%0,%1,%2,%3}, {%4,%5,%6,%7}, {%8,%9}, {%0,%1,%2,%3};\n"
                 : "+f"(d[0]), "+f"(d[1]), "+f"(d[2]), "+f"(d[3])
                 : "r"(a0), "r"(a1), "r"(a2), "r"(a3), "r"(b0), "r"(b1));
}

// ---------------- kernel 0: trig table -------------------------------------
__global__ void k_tab() {
    int m = blockIdx.x * blockDim.x + threadIdx.x;
    if (m < TT) {
        float s, c;
        sincospif((float)m * (1.0f / 2048.0f), &s, &c);
        g_tab[m] = make_float2(c, s);
    }
}

// ---------------- kernel 0b: weights -> tf32 bits ---------------------------
__global__ void k_prep(const float* __restrict__ w1, const float* __restrict__ w2) {
    int i = blockIdx.x * blockDim.x + threadIdx.x;
    if (i < KK * HH) g_w1t[i] = f2tf32(w1[KK * HH + i]);   // rows 128..255
    if (i < HH * DD) g_w2t[i] = f2tf32(w2[i]);
}

// ---------------- kernel 1: DFT (one block per (b,f)) -----------------------
__global__ void k_dft(const int* __restrict__ byte_ids,
                      const float* __restrict__ freq_bands) {
    int f = blockIdx.x;
    int b = blockIdx.y;
    int tid = threadIdx.x;  // 128 threads

    float re = 0.f, im = 0.f;
    for (int t = tid; t < TT; t += 128) {
        float s = (float)byte_ids[b * TT + t] * (1.0f / 127.5f) - 1.0f;
        int m = (f * t) & (TT - 1);
        float2 cs = g_tab[m];
        re += s * cs.x;
        im -= s * cs.y;
    }
    #pragma unroll
    for (int o = 16; o > 0; o >>= 1) {
        re += __shfl_xor_sync(0xffffffffu, re, o);
        im += __shfl_xor_sync(0xffffffffu, im, o);
    }
    __shared__ float sre[4], sim[4];
    if ((tid & 31) == 0) { sre[tid >> 5] = re; sim[tid >> 5] = im; }
    __syncthreads();
    if (tid == 0) {
        re = sre[0] + sre[1] + sre[2] + sre[3];
        im = sim[0] + sim[1] + sim[2] + sim[3];
        float mr = sqrtf(re * re + im * im);
        float s0, c0;
        if (mr > 0.f) { s0 = im / mr; c0 = re / mr; }
        else          { s0 = 0.f;    c0 = 1.f;    }
        g_mag[b * KK + f]  = mr * freq_bands[f];
        g_s0c0[b * KK + f] = make_float2(s0, c0);
    }
}

// ---------------- kernel 2: base = mag @ w1[:128] + b1 (exact fp32) ---------
__global__ void k_base(const float* __restrict__ w1, const float* __restrict__ b1) {
    int b = blockIdx.x;
    int j = threadIdx.x;  // 512 threads
    __shared__ float mg[KK];
    if (threadIdx.x < KK) mg[threadIdx.x] = g_mag[b * KK + threadIdx.x];
    __syncthreads();
    float acc = b1[j];
    #pragma unroll 4
    for (int f = 0; f < KK; ++f) acc += mg[f] * w1[f * HH + j];
    g_base[b * HH + j] = acc;
}

// ---------------- kernel 3: fused feats->MMA1->LN->GELU->MMA2 ---------------
// smem word layout:
//   sa   [64][132]  unsigned tf32  (A of GEMM1; aliased as weight buf1 in GEMM2)
//   sG   [64][516]  float h  -> tf32 g  (epilogue/LN/A of GEMM2)
//   wb   [32][264]  unsigned tf32 weight staging (GEMM1: two 16-row bufs)
//   sbase[512]      float
#define SA_STR 132
#define SG_STR 516
#define WB_STR 264
#define OFF_SA   0
#define OFF_SG   (TBLK * SA_STR)                 // 8448
#define OFF_WB   (OFF_SG + TBLK * SG_STR)        // 41472
#define OFF_BASE (OFF_WB + 32 * WB_STR)          // 49920
#define SM_WORDS (OFF_BASE + HH)                 // 50432 words = 201728 B

__global__ void __launch_bounds__(NTHR, 1)
k_main(const float* __restrict__ b2,
       const float* __restrict__ gamma,
       const float* __restrict__ beta,
       float* __restrict__ out) {
    extern __shared__ float smem[];
    unsigned* sa   = (unsigned*)smem + OFF_SA;
    float*    sGf  = smem + OFF_SG;
    unsigned* sGu  = (unsigned*)smem + OFF_SG;
    unsigned* wb   = (unsigned*)smem + OFF_WB;
    unsigned* wbA  = (unsigned*)smem + OFF_SA;   // GEMM2 second weight buffer
    float*    sbase = smem + OFF_BASE;

    int tid  = threadIdx.x;
    int lane = tid & 31, warp = tid >> 5;
    int b = blockIdx.y, t0 = blockIdx.x * TBLK;
    int mw = warp & 1, nw = warp >> 1;           // warp tile: rows mw*32, cols nw*64
    int gid = lane >> 2, t4 = lane & 3;

    // ---- feats: a[t][f] = sin(phase0 + 2*pi*f*(t0+t)/T), stored as tf32 ----
    for (int e = tid; e < TBLK * KK; e += NTHR) {
        int t = e >> 7, f = e & (KK - 1);
        int m = (f * (t0 + t)) & (TT - 1);
        float2 cs = g_tab[m];
        float2 sc = g_s0c0[b * KK + f];
        sa[t * SA_STR + f] = f2tf32(sc.x * cs.x + sc.y * cs.y);
    }
    for (int j = tid; j < HH; j += NTHR) sbase[j] = g_base[b * HH + j];
    __syncthreads();

    // =========================== GEMM1 =====================================
    // h[64][512] = a[64][128] @ w1s[128][512] + base, two N-passes of 256
    {
        int srow = tid >> 4, scol = tid & 15;    // stage: 16 rows x 256 cols
        for (int p = 0; p < 2; ++p) {
            int n0 = p * 256;
            float acc[2][8][4];
            #pragma unroll
            for (int mt = 0; mt < 2; ++mt)
                #pragma unroll
                for (int nt = 0; nt < 8; ++nt)
                    #pragma unroll
                    for (int q = 0; q < 4; ++q) acc[mt][nt][q] = 0.f;

            uint4 rg[4];
            const uint4* wsrc = (const uint4*)g_w1t;
            // prologue: chunk 0 -> buf0
            #pragma unroll
            for (int i = 0; i < 4; ++i)
                rg[i] = wsrc[srow * (HH / 4) + (n0 >> 2) + scol + 16 * i];
            #pragma unroll
            for (int i = 0; i < 4; ++i)
                ((uint4*)wb)[srow * (WB_STR / 4) + scol + 16 * i] = rg[i];
            __syncthreads();

            for (int c = 0; c < 8; ++c) {
                int pb = c & 1;
                if (c < 7) {
                    #pragma unroll
                    for (int i = 0; i < 4; ++i)
                        rg[i] = wsrc[((c + 1) * 16 + srow) * (HH / 4) + (n0 >> 2) + scol + 16 * i];
                }
                const unsigned* wbc = wb + pb * 16 * WB_STR;
                #pragma unroll
                for (int kk = 0; kk < 16; kk += 8) {
                    int kg = c * 16 + kk;
                    unsigned a[2][4];
                    #pragma unroll
                    for (int mt = 0; mt < 2; ++mt) {
                        int rb = mw * 32 + mt * 16;
                        a[mt][0] = sa[(rb + gid)     * SA_STR + kg + t4];
                        a[mt][1] = sa[(rb + gid + 8) * SA_STR + kg + t4];
                        a[mt][2] = sa[(rb + gid)     * SA_STR + kg + t4 + 4];
                        a[mt][3] = sa[(rb + gid + 8) * SA_STR + kg + t4 + 4];
                    }
                    #pragma unroll
                    for (int nt = 0; nt < 8; ++nt) {
                        int nb = nw * 64 + nt * 8;
                        unsigned b0 = wbc[(kk + t4)     * WB_STR + nb + gid];
                        unsigned b1 = wbc[(kk + t4 + 4) * WB_STR + nb + gid];
                        mma8(acc[0][nt], a[0][0], a[0][1], a[0][2], a[0][3], b0, b1);
                        mma8(acc[1][nt], a[1][0], a[1][1], a[1][2], a[1][3], b0, b1);
                    }
                }
                if (c < 7) {
                    int pb2 = (c + 1) & 1;
                    #pragma unroll
                    for (int i = 0; i < 4; ++i)
                        ((uint4*)wb)[pb2 * 16 * (WB_STR / 4) + srow * (WB_STR / 4) + scol + 16 * i] = rg[i];
                }
                __syncthreads();
            }
            // epilogue: h = acc + base -> sG (fp32)
            #pragma unroll
            for (int mt = 0; mt < 2; ++mt) {
                int r0 = mw * 32 + mt * 16 + gid;
                #pragma unroll
                for (int nt = 0; nt < 8; ++nt) {
                    int col = n0 + nw * 64 + nt * 8 + 2 * t4;
                    float2 v0 = make_float2(acc[mt][nt][0] + sbase[col],
                                            acc[mt][nt][1] + sbase[col + 1]);
                    float2 v1 = make_float2(acc[mt][nt][2] + sbase[col],
                                            acc[mt][nt][3] + sbase[col + 1]);
                    *(float2*)(sGf + r0 * SG_STR + col)       = v0;
                    *(float2*)(sGf + (r0 + 8) * SG_STR + col) = v1;
                }
            }
        }
    }
    __syncthreads();

    // ---- LayerNorm + exact GELU; store back as tf32 bits ----
    {
        int row = tid >> 2, part = tid & 3;
        float* hr = sGf + row * SG_STR + part * 128;
        float sum = 0.f, sq = 0.f;
        #pragma unroll 4
        for (int i = 0; i < 128; ++i) { float v = hr[i]; sum += v; sq += v * v; }
        #pragma unroll
        for (int o = 1; o < 4; o <<= 1) {
            sum += __shfl_xor_sync(0xffffffffu, sum, o);
            sq  += __shfl_xor_sync(0xffffffffu, sq,  o);
        }
        float mu  = sum * (1.0f / 512.0f);
        float var = sq * (1.0f / 512.0f) - mu * mu;
        float rs  = rsqrtf(var + 1e-5f);
        unsigned* hu = (unsigned*)hr;
        #pragma unroll 4
        for (int i = 0; i < 128; ++i) {
            int j = part * 128 + i;
            float v = (hr[i] - mu) * rs * gamma[j] + beta[j];
            hu[i] = f2tf32(v * normcdff(v));   // exact GELU
        }
    }
    __syncthreads();

    // =========================== GEMM2 =====================================
    // out[64][256] = g[64][512] @ w2[512][256] + b2, single N-pass
    {
        float acc[2][8][4];
        #pragma unroll
        for (int mt = 0; mt < 2; ++mt)
            #pragma unroll
            for (int nt = 0; nt < 8; ++nt)
                #pragma unroll
                for (int q = 0; q < 4; ++q) acc[mt][nt][q] = 0.f;

        int srow = tid >> 3, scol = tid & 7;     // stage: 32 rows x 256 cols
        uint4 rg[8];
        const uint4* wsrc = (const uint4*)g_w2t;
        // prologue: chunk 0 -> wb (buf0)
        #pragma unroll
        for (int i = 0; i < 8; ++i)
            rg[i] = wsrc[srow * (DD / 4) + scol + 8 * i];
        #pragma unroll
        for (int i = 0; i < 8; ++i)
            ((uint4*)wb)[srow * (WB_STR / 4) + scol + 8 * i] = rg[i];
        __syncthreads();

        for (int c = 0; c < 16; ++c) {
            const unsigned* wbc = (c & 1) ? wbA : wb;
            if (c < 15) {
                #pragma unroll
                for (int i = 0; i < 8; ++i)
                    rg[i] = wsrc[((c + 1) * 32 + srow) * (DD / 4) + scol + 8 * i];
            }
            #pragma unroll
            for (int kk = 0; kk < 32; kk += 8) {
                int kg = c * 32 + kk;
                unsigned a[2][4];
                #pragma unroll
                for (int mt = 0; mt < 2; ++mt) {
                    int rb = mw * 32 + mt * 16;
                    a[mt][0] = sGu[(rb + gid)     * SG_STR + kg + t4];
                    a[mt][1] = sGu[(rb + gid + 8) * SG_STR + kg + t4];
                    a[mt][2] = sGu[(rb + gid)     * SG_STR + kg + t4 + 4];
                    a[mt][3] = sGu[(rb + gid + 8) * SG_STR + kg + t4 + 4];
                }
                #pragma unroll
                for (int nt = 0; nt < 8; ++nt) {
                    int nb = nw * 64 + nt * 8;
                    unsigned b0 = wbc[(kk + t4)     * WB_STR + nb + gid];
                    unsigned b1 = wbc[(kk + t4 + 4) * WB_STR + nb + gid];
                    mma8(acc[0][nt], a[0][0], a[0][1], a[0][2], a[0][3], b0, b1);
                    mma8(acc[1][nt], a[1][0], a[1][1], a[1][2], a[1][3], b0, b1);
                }
            }
            if (c < 15) {
                unsigned* wbn = ((c + 1) & 1) ? wbA : wb;
                #pragma unroll
                for (int i = 0; i < 8; ++i)
                    ((uint4*)wbn)[srow * (WB_STR / 4) + scol + 8 * i] = rg[i];
            }
            __syncthreads();
        }

        // epilogue: + b2 -> out
        #pragma unroll
        for (int mt = 0; mt < 2; ++mt) {
            int r0 = t0 + mw * 32 + mt * 16 + gid;
            #pragma unroll
            for (int nt = 0; nt < 8; ++nt) {
                int col = nw * 64 + nt * 8 + 2 * t4;
                float2 bb = *(const float2*)(b2 + col);
                float2 o0 = make_float2(acc[mt][nt][0] + bb.x, acc[mt][nt][1] + bb.y);
                float2 o1 = make_float2(acc[mt][nt][2] + bb.x, acc[mt][nt][3] + bb.y);
                *(float2*)(out + ((size_t)b * TT + r0) * DD + col)     = o0;
                *(float2*)(out + ((size_t)b * TT + r0 + 8) * DD + col) = o1;
            }
        }
    }
}

// ---------------- launch ----------------------------------------------------
extern "C" void kernel_launch(void* const* d_in, const int* in_sizes, int n_in,
                              void* d_out, int out_size) {
    const int*   byte_ids   = (const int*)d_in[0];
    const float* freq_bands = (const float*)d_in[1];
    const float* w1         = (const float*)d_in[2];
    const float* b1         = (const float*)d_in[3];
    const float* gamma      = (const float*)d_in[4];
    const float* beta       = (const float*)d_in[5];
    const float* w2         = (const float*)d_in[6];
    const float* b2         = (const float*)d_in[7];
    float* out = (float*)d_out;

    size_t smem_bytes = (size_t)SM_WORDS * sizeof(float);  // ~197 KB
    cudaFuncSetAttribute(k_main, cudaFuncAttributeMaxDynamicSharedMemorySize,
                         (int)smem_bytes);

    k_tab<<<(TT + 255) / 256, 256>>>();
    k_prep<<<(HH * DD + 255) / 256, 256>>>(w1, w2);
    k_dft<<<dim3(KK, BB), 128>>>(byte_ids, freq_bands);
    k_base<<<BB, HH>>>(w1, b1);
    k_main<<<dim3(TT / TBLK, BB), NTHR, smem_bytes>>>(b2, gamma, beta, out);
}

// round 7
// speedup vs baseline: 4.1092x; 1.0343x over previous
#include <cuda_runtime.h>
#include <math.h>

#define BB 32
#define TT 4096
#define DD 256
#define KK 128         // frequency count = D/2
#define HH 512         // hidden = 2*D
#define TBLK 64        // tokens per block in main kernel
#define NTHR 256

// ---------------- scratch (global __device__, no allocation) ----------------
__device__ float2 g_tab[TT];        // (cos(2*pi*m/T), sin(2*pi*m/T))
__device__ float2 g_s0c0[BB * KK];  // (sin(phase0), cos(phase0))
__device__ float  g_mag[BB * KK];   // |X| * freq_bands
__device__ float  g_base[BB * HH];  // mag @ w1[:128,:] + b1  (exact fp32 path)
__device__ unsigned g_w1t[KK * HH]; // tf32 bits of w1 rows 128..255
__device__ unsigned g_w2t[HH * DD]; // tf32 bits of w2

__device__ __forceinline__ unsigned f2tf32(float x) {
    unsigned r;
    asm("cvt.rna.tf32.f32 %0, %1;" : "=r"(r) : "f"(x));
    return r;
}

__device__ __forceinline__ void mma8(float* d,
                                     unsigned a0, unsigned a1, unsigned a2, unsigned a3,
                                     unsigned b0, unsigned b1) {
    asm volatile("mma.sync.aligned.m16n8k8.row.col.f32.tf32.tf32.f32 "
                 "{%0,%1,%2,%3}, {%4,%5,%6,%7}, {%8,%9}, {%0,%1,%2,%3};\n"
                 : "+f"(d[0]), "+f"(d[1]), "+f"(d[2]), "+f"(d[3])
                 : "r"(a0), "r"(a1), "r"(a2), "r"(a3), "r"(b0), "r"(b1));
}

// ---------------- kernel 0: trig table -------------------------------------
__global__ void k_tab() {
    int m = blockIdx.x * blockDim.x + threadIdx.x;
    if (m < TT) {
        float s, c;
        sincospif((float)m * (1.0f / 2048.0f), &s, &c);
        g_tab[m] = make_float2(c, s);
    }
}

// ---------------- kernel 0b: weights -> tf32 bits ---------------------------
__global__ void k_prep(const float* __restrict__ w1, const float* __restrict__ w2) {
    int i = blockIdx.x * blockDim.x + threadIdx.x;
    if (i < KK * HH) g_w1t[i] = f2tf32(w1[KK * HH + i]);   // rows 128..255
    if (i < HH * DD) g_w2t[i] = f2tf32(w2[i]);
}

// ---------------- kernel 1: DFT — signal staged in smem, 1 warp per freq ----
__global__ void k_dft(const int* __restrict__ byte_ids,
                      const float* __restrict__ freq_bands) {
    __shared__ float sig[TT];          // 16 KB
    int fg = blockIdx.x;               // 0..15 (8 freqs each)
    int b  = blockIdx.y;
    int tid = threadIdx.x;             // 256

    for (int t = tid; t < TT; t += 256)
        sig[t] = (float)byte_ids[b * TT + t] * (1.0f / 127.5f) - 1.0f;
    __syncthreads();

    int w = tid >> 5, lane = tid & 31;
    int f = fg * 8 + w;
    float re = 0.f, im = 0.f;
    #pragma unroll 4
    for (int t = lane; t < TT; t += 32) {
        int m = (f * t) & (TT - 1);
        float2 cs = g_tab[m];
        float s = sig[t];
        re += s * cs.x;
        im -= s * cs.y;
    }
    #pragma unroll
    for (int o = 16; o > 0; o >>= 1) {
        re += __shfl_xor_sync(0xffffffffu, re, o);
        im += __shfl_xor_sync(0xffffffffu, im, o);
    }
    if (lane == 0) {
        float mr = sqrtf(re * re + im * im);
        float s0, c0;
        if (mr > 0.f) { s0 = im / mr; c0 = re / mr; }
        else          { s0 = 0.f;    c0 = 1.f;    }
        g_mag[b * KK + f]  = mr * freq_bands[f];
        g_s0c0[b * KK + f] = make_float2(s0, c0);
    }
}

// ---------------- kernel 2: base = mag @ w1[:128] + b1 (exact fp32) ---------
__global__ void k_base(const float* __restrict__ w1, const float* __restrict__ b1) {
    int b = blockIdx.x;
    int j = blockIdx.y * 128 + threadIdx.x;   // 128 threads, 4 col-slices
    __shared__ float mg[KK];
    mg[threadIdx.x] = g_mag[b * KK + threadIdx.x];
    __syncthreads();
    float acc = b1[j];
    #pragma unroll 4
    for (int f = 0; f < KK; ++f) acc += mg[f] * w1[f * HH + j];
    g_base[b * HH + j] = acc;
}

// ---------------- kernel 3: fused feats->MMA1->LN->GELU->MMA2 ---------------
// smem word layout:
//   sa   [64][132]  unsigned tf32  (A of GEMM1; aliased as weight buf1 in GEMM2)
//   sG   [64][516]  float h  -> tf32 g  (epilogue/LN/A of GEMM2)
//   wb   [32][264]  unsigned tf32 weight staging (GEMM1: two 16-row bufs)
//   sbase[512] sgam[512] sbet[512]  float
#define SA_STR 132
#define SG_STR 516
#define WB_STR 264
#define OFF_SA   0
#define OFF_SG   (TBLK * SA_STR)                 // 8448
#define OFF_WB   (OFF_SG + TBLK * SG_STR)        // 41472
#define OFF_BASE (OFF_WB + 32 * WB_STR)          // 49920
#define OFF_GAM  (OFF_BASE + HH)
#define OFF_BET  (OFF_GAM + HH)
#define SM_WORDS (OFF_BET + HH)                  // 51456 words = 205824 B

__global__ void __launch_bounds__(NTHR, 1)
k_main(const float* __restrict__ b2,
       const float* __restrict__ gamma,
       const float* __restrict__ beta,
       float* __restrict__ out) {
    extern __shared__ float smem[];
    unsigned* sa   = (unsigned*)smem + OFF_SA;
    float*    sGf  = smem + OFF_SG;
    unsigned* sGu  = (unsigned*)smem + OFF_SG;
    unsigned* wb   = (unsigned*)smem + OFF_WB;
    unsigned* wbA  = (unsigned*)smem + OFF_SA;   // GEMM2 second weight buffer
    float*    sbase = smem + OFF_BASE;
    float*    sgam  = smem + OFF_GAM;
    float*    sbet  = smem + OFF_BET;

    int tid  = threadIdx.x;
    int lane = tid & 31, warp = tid >> 5;
    int b = blockIdx.y, t0 = blockIdx.x * TBLK;
    int mw = warp & 1, nw = warp >> 1;           // warp tile: rows mw*32, cols nw*64
    int gid = lane >> 2, t4 = lane & 3;

    // ---- feats: a[t][f] = sin(phase0 + 2*pi*f*(t0+t)/T), stored as tf32 ----
    for (int e = tid; e < TBLK * KK; e += NTHR) {
        int t = e >> 7, f = e & (KK - 1);
        int m = (f * (t0 + t)) & (TT - 1);
        float2 cs = g_tab[m];
        float2 sc = g_s0c0[b * KK + f];
        sa[t * SA_STR + f] = f2tf32(sc.x * cs.x + sc.y * cs.y);
    }
    for (int j = tid; j < HH; j += NTHR) {
        sbase[j] = g_base[b * HH + j];
        sgam[j]  = gamma[j];
        sbet[j]  = beta[j];
    }
    __syncthreads();

    // =========================== GEMM1 =====================================
    // h[64][512] = a[64][128] @ w1s[128][512] + base, two N-passes of 256
    {
        int srow = tid >> 4, scol = tid & 15;    // stage: 16 rows x 256 cols
        for (int p = 0; p < 2; ++p) {
            int n0 = p * 256;
            float acc[2][8][4];
            #pragma unroll
            for (int mt = 0; mt < 2; ++mt)
                #pragma unroll
                for (int nt = 0; nt < 8; ++nt)
                    #pragma unroll
                    for (int q = 0; q < 4; ++q) acc[mt][nt][q] = 0.f;

            uint4 rg[4];
            const uint4* wsrc = (const uint4*)g_w1t;
            // prologue: chunk 0 -> buf0
            #pragma unroll
            for (int i = 0; i < 4; ++i)
                rg[i] = wsrc[srow * (HH / 4) + (n0 >> 2) + scol + 16 * i];
            #pragma unroll
            for (int i = 0; i < 4; ++i)
                ((uint4*)wb)[srow * (WB_STR / 4) + scol + 16 * i] = rg[i];
            __syncthreads();

            for (int c = 0; c < 8; ++c) {
                int pb = c & 1;
                if (c < 7) {
                    #pragma unroll
                    for (int i = 0; i < 4; ++i)
                        rg[i] = wsrc[((c + 1) * 16 + srow) * (HH / 4) + (n0 >> 2) + scol + 16 * i];
                }
                const unsigned* wbc = wb + pb * 16 * WB_STR;
                #pragma unroll
                for (int kk = 0; kk < 16; kk += 8) {
                    int kg = c * 16 + kk;
                    unsigned a[2][4];
                    #pragma unroll
                    for (int mt = 0; mt < 2; ++mt) {
                        int rb = mw * 32 + mt * 16;
                        a[mt][0] = sa[(rb + gid)     * SA_STR + kg + t4];
                        a[mt][1] = sa[(rb + gid + 8) * SA_STR + kg + t4];
                        a[mt][2] = sa[(rb + gid)     * SA_STR + kg + t4 + 4];
                        a[mt][3] = sa[(rb + gid + 8) * SA_STR + kg + t4 + 4];
                    }
                    #pragma unroll
                    for (int nt = 0; nt < 8; ++nt) {
                        int nb = nw * 64 + nt * 8;
                        unsigned b0 = wbc[(kk + t4)     * WB_STR + nb + gid];
                        unsigned b1 = wbc[(kk + t4 + 4) * WB_STR + nb + gid];
                        mma8(acc[0][nt], a[0][0], a[0][1], a[0][2], a[0][3], b0, b1);
                        mma8(acc[1][nt], a[1][0], a[1][1], a[1][2], a[1][3], b0, b1);
                    }
                }
                if (c < 7) {
                    int pb2 = (c + 1) & 1;
                    #pragma unroll
                    for (int i = 0; i < 4; ++i)
                        ((uint4*)wb)[pb2 * 16 * (WB_STR / 4) + srow * (WB_STR / 4) + scol + 16 * i] = rg[i];
                }
                __syncthreads();
            }
            // epilogue: h = acc + base -> sG (fp32)
            #pragma unroll
            for (int mt = 0; mt < 2; ++mt) {
                int r0 = mw * 32 + mt * 16 + gid;
                #pragma unroll
                for (int nt = 0; nt < 8; ++nt) {
                    int col = n0 + nw * 64 + nt * 8 + 2 * t4;
                    float2 v0 = make_float2(acc[mt][nt][0] + sbase[col],
                                            acc[mt][nt][1] + sbase[col + 1]);
                    float2 v1 = make_float2(acc[mt][nt][2] + sbase[col],
                                            acc[mt][nt][3] + sbase[col + 1]);
                    *(float2*)(sGf + r0 * SG_STR + col)       = v0;
                    *(float2*)(sGf + (r0 + 8) * SG_STR + col) = v1;
                }
            }
        }
    }
    __syncthreads();

    // ---- LayerNorm + exact GELU (erf form); store back as tf32 bits ----
    {
        int row = tid >> 2, part = tid & 3;
        float* hr = sGf + row * SG_STR + part * 128;
        float sum = 0.f, sq = 0.f;
        #pragma unroll 4
        for (int i = 0; i < 128; ++i) { float v = hr[i]; sum += v; sq += v * v; }
        #pragma unroll
        for (int o = 1; o < 4; o <<= 1) {
            sum += __shfl_xor_sync(0xffffffffu, sum, o);
            sq  += __shfl_xor_sync(0xffffffffu, sq,  o);
        }
        float mu  = sum * (1.0f / 512.0f);
        float var = sq * (1.0f / 512.0f) - mu * mu;
        float rs  = rsqrtf(var + 1e-5f);
        unsigned* hu = (unsigned*)hr;
        #pragma unroll 4
        for (int i = 0; i < 128; ++i) {
            int j = part * 128 + i;
            float v = (hr[i] - mu) * rs * sgam[j] + sbet[j];
            float g = 0.5f * v * (1.0f + erff(v * 0.70710678118654752f));
            hu[i] = f2tf32(g);   // exact GELU via erf
        }
    }
    __syncthreads();

    // =========================== GEMM2 =====================================
    // out[64][256] = g[64][512] @ w2[512][256] + b2, single N-pass
    {
        float acc[2][8][4];
        #pragma unroll
        for (int mt = 0; mt < 2; ++mt)
            #pragma unroll
            for (int nt = 0; nt < 8; ++nt)
                #pragma unroll
                for (int q = 0; q < 4; ++q) acc[mt][nt][q] = 0.f;

        int srow = tid >> 3, scol = tid & 7;     // stage: 32 rows x 256 cols
        uint4 rg[8];
        const uint4* wsrc = (const uint4*)g_w2t;
        // prologue: chunk 0 -> wb (buf0)
        #pragma unroll
        for (int i = 0; i < 8; ++i)
            rg[i] = wsrc[srow * (DD / 4) + scol + 8 * i];
        #pragma unroll
        for (int i = 0; i < 8; ++i)
            ((uint4*)wb)[srow * (WB_STR / 4) + scol + 8 * i] = rg[i];
        __syncthreads();

        for (int c = 0; c < 16; ++c) {
            const unsigned* wbc = (c & 1) ? wbA : wb;
            if (c < 15) {
                #pragma unroll
                for (int i = 0; i < 8; ++i)
                    rg[i] = wsrc[((c + 1) * 32 + srow) * (DD / 4) + scol + 8 * i];
            }
            #pragma unroll
            for (int kk = 0; kk < 32; kk += 8) {
                int kg = c * 32 + kk;
                unsigned a[2][4];
                #pragma unroll
                for (int mt = 0; mt < 2; ++mt) {
                    int rb = mw * 32 + mt * 16;
                    a[mt][0] = sGu[(rb + gid)     * SG_STR + kg + t4];
                    a[mt][1] = sGu[(rb + gid + 8) * SG_STR + kg + t4];
                    a[mt][2] = sGu[(rb + gid)     * SG_STR + kg + t4 + 4];
                    a[mt][3] = sGu[(rb + gid + 8) * SG_STR + kg + t4 + 4];
                }
                #pragma unroll
                for (int nt = 0; nt < 8; ++nt) {
                    int nb = nw * 64 + nt * 8;
                    unsigned b0 = wbc[(kk + t4)     * WB_STR + nb + gid];
                    unsigned b1 = wbc[(kk + t4 + 4) * WB_STR + nb + gid];
                    mma8(acc[0][nt], a[0][0], a[0][1], a[0][2], a[0][3], b0, b1);
                    mma8(acc[1][nt], a[1][0], a[1][1], a[1][2], a[1][3], b0, b1);
                }
            }
            if (c < 15) {
                unsigned* wbn = ((c + 1) & 1) ? wbA : wb;
                #pragma unroll
                for (int i = 0; i < 8; ++i)
                    ((uint4*)wbn)[srow * (WB_STR / 4) + scol + 8 * i] = rg[i];
            }
            __syncthreads();
        }

        // epilogue: + b2 -> out
        #pragma unroll
        for (int mt = 0; mt < 2; ++mt) {
            int r0 = t0 + mw * 32 + mt * 16 + gid;
            #pragma unroll
            for (int nt = 0; nt < 8; ++nt) {
                int col = nw * 64 + nt * 8 + 2 * t4;
                float2 bb = *(const float2*)(b2 + col);
                float2 o0 = make_float2(acc[mt][nt][0] + bb.x, acc[mt][nt][1] + bb.y);
                float2 o1 = make_float2(acc[mt][nt][2] + bb.x, acc[mt][nt][3] + bb.y);
                *(float2*)(out + ((size_t)b * TT + r0) * DD + col)     = o0;
                *(float2*)(out + ((size_t)b * TT + r0 + 8) * DD + col) = o1;
            }
        }
    }
}

// ---------------- launch ----------------------------------------------------
extern "C" void kernel_launch(void* const* d_in, const int* in_sizes, int n_in,
                              void* d_out, int out_size) {
    const int*   byte_ids   = (const int*)d_in[0];
    const float* freq_bands = (const float*)d_in[1];
    const float* w1         = (const float*)d_in[2];
    const float* b1         = (const float*)d_in[3];
    const float* gamma      = (const float*)d_in[4];
    const float* beta       = (const float*)d_in[5];
    const float* w2         = (const float*)d_in[6];
    const float* b2         = (const float*)d_in[7];
    float* out = (float*)d_out;

    size_t smem_bytes = (size_t)SM_WORDS * sizeof(float);  // ~201 KB
    cudaFuncSetAttribute(k_main, cudaFuncAttributeMaxDynamicSharedMemorySize,
                         (int)smem_bytes);

    k_tab<<<(TT + 255) / 256, 256>>>();
    k_prep<<<(HH * DD + 255) / 256, 256>>>(w1, w2);
    k_dft<<<dim3(KK / 8, BB), 256>>>(byte_ids, freq_bands);
    k_base<<<dim3(BB, 4), 128>>>(w1, b1);
    k_main<<<dim3(TT / TBLK, BB), NTHR, smem_bytes>>>(b2, gamma, beta, out);
}